// round 16
// baseline (speedup 1.0000x reference)
#include <cuda_runtime.h>
#include <cuda_bf16.h>
#include <cstdint>

// Problem constants
#define BATCH 2
#define SEQ   2048
#define CDIM  1024
#define NHEAD 16
#define HDIM  64
#define MROWS (BATCH*SEQ)      // 4096
#define BSIZE 102
#define QKV_SZ (BATCH*NHEAD*SEQ*HDIM)

// Scratch (device globals: allocation-free)
// slot 0: Q [B,H,T,D]; slot 1: K [B,H,T,D]; slot 2: V TRANSPOSED [B,H,D,T]
__device__ float g_qkv[3*QKV_SZ];
__device__ float g_att[MROWS*CDIM];           // [B,T,C]  (tf32-rounded)
__device__ float g_xr[MROWS*CDIM];            // tf32-rounded x
__device__ float g_wr[4*CDIM*CDIM];           // tf32-rounded Wq,Wk,Wv,Wp

// ---------------------------------------------------------------------------
// helpers
// ---------------------------------------------------------------------------
__device__ __forceinline__ float f2tf32(float f) {
    uint32_t r;
    asm("cvt.rna.tf32.f32 %0, %1;" : "=r"(r) : "f"(f));
    return __uint_as_float(r);
}

// single-instruction exp2 (MUFU.EX2)
__device__ __forceinline__ float ex2(float x) {
    float r;
    asm("ex2.approx.f32 %0, %1;" : "=f"(r) : "f"(x));
    return r;
}

#define MMA_TF32(c0,c1,c2,c3,a0,a1,a2,a3,b0,b1)                          \
    asm volatile("mma.sync.aligned.m16n8k8.row.col.f32.tf32.tf32.f32 "  \
                 "{%0,%1,%2,%3},{%4,%5,%6,%7},{%8,%9},{%0,%1,%2,%3};"   \
                 : "+f"(c0), "+f"(c1), "+f"(c2), "+f"(c3)               \
                 : "r"(a0), "r"(a1), "r"(a2), "r"(a3), "r"(b0), "r"(b1))

__device__ __forceinline__ void ldsm4(uint32_t& r0, uint32_t& r1,
                                      uint32_t& r2, uint32_t& r3,
                                      const void* p) {
    uint32_t s = (uint32_t)__cvta_generic_to_shared(p);
    asm volatile("ldmatrix.sync.aligned.m8n8.x4.shared.b16 {%0,%1,%2,%3}, [%4];"
                 : "=r"(r0), "=r"(r1), "=r"(r2), "=r"(r3) : "r"(s));
}

__device__ __forceinline__ void cp16(void* smem_dst, const void* gptr) {
    uint32_t s = (uint32_t)__cvta_generic_to_shared(smem_dst);
    asm volatile("cp.async.cg.shared.global [%0], [%1], 16;" :: "r"(s), "l"(gptr));
}
#define CP_COMMIT() asm volatile("cp.async.commit_group;")
#define CP_WAIT(n)  asm volatile("cp.async.wait_group %0;" :: "n"(n))

// ---------------------------------------------------------------------------
// Fused prep: round x and the four W's to tf32 in one launch.
// ---------------------------------------------------------------------------
__global__ void prep_round(const float4* __restrict__ x,
                           const float4* __restrict__ wq,
                           const float4* __restrict__ wk,
                           const float4* __restrict__ wv,
                           const float4* __restrict__ wp,
                           float4* __restrict__ xr,
                           float4* __restrict__ wr)
{
    const int seg = blockIdx.y;
    const float4* src;
    float4* dst;
    int n4;
    if (seg == 0) { src = x;  dst = xr; n4 = MROWS * CDIM / 4; }
    else {
        src = (seg == 1) ? wq : (seg == 2) ? wk : (seg == 3) ? wv : wp;
        dst = wr + (size_t)(seg - 1) * (CDIM * CDIM / 4);
        n4  = CDIM * CDIM / 4;
    }
    for (int i = blockIdx.x * blockDim.x + threadIdx.x; i < n4;
         i += gridDim.x * blockDim.x) {
        float4 v = src[i];
        v.x = f2tf32(v.x); v.y = f2tf32(v.y);
        v.z = f2tf32(v.z); v.w = f2tf32(v.w);
        dst[i] = v;
    }
}

// ---------------------------------------------------------------------------
// tf32 tensor-core GEMM body, 3-stage cp.async pipeline (one sync per tile),
// ldmatrix A-frags. C[M,N] = A[M,K] @ W[K,N] + bias.  M=4096, N=K=1024.
// CTA 128x128, K-tile 32, 4 warps (64x64 warp tile), 128 threads, 2 CTA/SM.
// mode 0: scatter rounded output into [B,H,T,D]
// mode 1: row-major fp32
// mode 2: scatter rounded output TRANSPOSED into [B,H,D,T] (for V)
// ---------------------------------------------------------------------------
#define BM 128
#define BN 128
#define BK 32
#define AS_LD 36
#define BS_LD 136
#define AS_SZ (BM*AS_LD)                    // 4608 floats
#define BS_SZ (BK*BS_LD)                    // 4352 floats
#define GSTAGES 3
#define GSMEM (GSTAGES*(AS_SZ + BS_SZ)*4)   // 107520 bytes

__device__ __forceinline__
void gemm_body(const float* __restrict__ A, const float* __restrict__ W,
               const float* __restrict__ bias, float* __restrict__ C, int mode)
{
    const int K = CDIM, N = CDIM;
    extern __shared__ float sm[];
    float* As = sm;                          // [3][AS_SZ]
    float* Bs = sm + GSTAGES * AS_SZ;        // [3][BS_SZ]

    const int tid  = threadIdx.x;
    const int rowBase = blockIdx.y * BM;
    const int colBase = blockIdx.x * BN;

    const int w    = tid >> 5;
    const int lane = tid & 31;
    const int g    = lane >> 2;
    const int tg   = lane & 3;
    const int wm   = (w >> 1) * 64;
    const int wn   = (w & 1) * 64;

    const int lm_row = ((lane >> 3) & 1) * 8 + (lane & 7);
    const int lm_col = (lane >> 4) * 4;

    float c[4][8][4] = {};
    const int ntiles = K / BK;

    auto issue = [&](int s, int kt) {
        const int k0 = kt * BK;
        #pragma unroll
        for (int i = 0; i < 8; ++i) {
            const int f = tid + i * 128;
            const int ar = f >> 3, ac = f & 7;
            cp16(&As[s * AS_SZ + ar * AS_LD + ac * 4],
                 &A[(size_t)(rowBase + ar) * K + k0 + ac * 4]);
            const int br = f >> 5, bc = f & 31;
            cp16(&Bs[s * BS_SZ + br * BS_LD + bc * 4],
                 &W[(size_t)(k0 + br) * N + colBase + bc * 4]);
        }
        CP_COMMIT();
    };

    // prologue: stages 0,1 in flight; tile 0 resident before loop
    issue(0, 0);
    issue(1, 1);
    CP_WAIT(1);
    __syncthreads();

    for (int kt = 0; kt < ntiles; ++kt) {
        const int s = kt % GSTAGES;
        const float* Ab = As + s * AS_SZ;
        const float* Bb = Bs + s * BS_SZ;

        #pragma unroll
        for (int ks = 0; ks < BK / 8; ++ks) {
            const int kb = ks * 8;
            uint32_t af[4][4];
            #pragma unroll
            for (int mi = 0; mi < 4; ++mi) {
                const int r = wm + mi * 16 + lm_row;
                ldsm4(af[mi][0], af[mi][1], af[mi][2], af[mi][3],
                      &Ab[r * AS_LD + kb + lm_col]);
            }
            uint32_t bf[8][2];
            #pragma unroll
            for (int ni = 0; ni < 8; ++ni) {
                const int n0 = wn + ni * 8 + g;
                bf[ni][0] = __float_as_uint(Bb[(kb + tg    ) * BS_LD + n0]);
                bf[ni][1] = __float_as_uint(Bb[(kb + tg + 4) * BS_LD + n0]);
            }
            #pragma unroll
            for (int mi = 0; mi < 4; ++mi)
                #pragma unroll
                for (int ni = 0; ni < 8; ++ni)
                    MMA_TF32(c[mi][ni][0], c[mi][ni][1], c[mi][ni][2], c[mi][ni][3],
                             af[mi][0], af[mi][1], af[mi][2], af[mi][3],
                             bf[ni][0], bf[ni][1]);
        }

        // issue tile kt+2 into the slot all warps finished reading at kt-1
        if (kt + 2 < ntiles) issue((kt + 2) % GSTAGES, kt + 2);
        else                 CP_COMMIT();          // keep group count aligned
        CP_WAIT(1);                                 // tile kt+1 resident
        __syncthreads();
    }

    #pragma unroll
    for (int mi = 0; mi < 4; ++mi) {
        #pragma unroll
        for (int ni = 0; ni < 8; ++ni) {
            #pragma unroll
            for (int e = 0; e < 4; ++e) {
                const int r  = rowBase + wm + mi * 16 + g + ((e >> 1) << 3);
                const int cc = colBase + wn + ni * 8 + 2 * tg + (e & 1);
                const float val = c[mi][ni][e] + bias[cc];
                if (mode == 0) {
                    const int b = r >> 11;
                    const int t = r & (SEQ - 1);
                    const int h = cc >> 6;
                    const int d = cc & (HDIM - 1);
                    C[(((size_t)b * NHEAD + h) * SEQ + t) * HDIM + d] = f2tf32(val);
                } else if (mode == 2) {
                    const int b = r >> 11;
                    const int t = r & (SEQ - 1);
                    const int h = cc >> 6;
                    const int d = cc & (HDIM - 1);
                    C[(((size_t)b * NHEAD + h) * HDIM + d) * SEQ + t] = f2tf32(val);
                } else {
                    C[(size_t)r * CDIM + cc] = val;
                }
            }
        }
    }
}

// Fused QKV GEMM: grid.z in {0,1,2} selects weight/bias/output slice.
// z==2 (V) scatters transposed [B,H,D,T].
__global__ __launch_bounds__(128)
void gemm_qkv(const float* __restrict__ A, const float* __restrict__ Wbase,
              const float* __restrict__ b0, const float* __restrict__ b1,
              const float* __restrict__ b2, float* __restrict__ outBase)
{
    const int z = blockIdx.z;
    const float* bias = (z == 0) ? b0 : (z == 1) ? b1 : b2;
    gemm_body(A, Wbase + (size_t)z * CDIM * CDIM, bias,
              outBase + (size_t)z * QKV_SZ, (z == 2) ? 2 : 0);
}

__global__ __launch_bounds__(128)
void gemm_proj(const float* __restrict__ A, const float* __restrict__ W,
               const float* __restrict__ bias, float* __restrict__ C)
{
    gemm_body(A, W, bias, C, 1);
}

// ---------------------------------------------------------------------------
// Tensor-core causal flash attention (tf32), 3-stage cp.async pipeline
// (ONE sync per key tile). grid = (SEQ/128, B*H), block = 128.
// Key tile 64. K [T,D] and V^T [D,T] both stride-68 smem; BOTH K and V
// B-fragments via ldmatrix.x4 (V is pre-transposed by the QKV GEMM).
// Softmax in exp2 domain via ex2.approx. Output tf32-rounded.
// ---------------------------------------------------------------------------
#define K_LD 68
#define V_LD 68
#define K_BUF (64*K_LD)                      // 4352 floats
#define V_BUF (64*V_LD)                      // 4352 floats
#define ASTAGES 3
#define ASMEM (ASTAGES*(K_BUF + V_BUF)*4)    // 104448 bytes

__global__ __launch_bounds__(128)
void attn_tc(float* __restrict__ out)
{
    const int qt   = gridDim.x - 1 - blockIdx.x;
    const int bh   = blockIdx.y;
    const int b    = bh >> 4;
    const int h    = bh & 15;
    const int tid  = threadIdx.x;
    const int warp = tid >> 5;
    const int lane = tid & 31;
    const int g    = lane >> 2;
    const int tg   = lane & 3;
    const int row_base = qt * 128 + warp * 32;

    extern __shared__ float smA[];
    float* KsB = smA;                        // [3][K_BUF]
    float* VsB = smA + ASTAGES * K_BUF;      // [3][V_BUF]

    const int klm_row = ((lane >> 4) << 3) + (lane & 7);
    const int klm_col = ((lane >> 3) & 1) * 4;

    const float* kt0 = g_qkv + 1 * QKV_SZ + (size_t)bh * SEQ * HDIM;   // [T,D]
    const float* vt0 = g_qkv + 2 * QKV_SZ + (size_t)bh * HDIM * SEQ;   // [D,T]

    // Q fragments scaled by (1/8)*log2(e): softmax runs in exp2 domain.
    const float QSCALE = 0.125f * 1.4426950408889634f;
    const float* qp = g_qkv + ((size_t)bh * SEQ + row_base) * HDIM;
    uint32_t Qa[2][8][4];
    #pragma unroll
    for (int mi = 0; mi < 2; ++mi) {
        #pragma unroll
        for (int kb = 0; kb < 8; ++kb) {
            Qa[mi][kb][0] = __float_as_uint(f2tf32(QSCALE * qp[(size_t)(mi*16 + g    ) * 64 + kb*8 + tg]));
            Qa[mi][kb][1] = __float_as_uint(f2tf32(QSCALE * qp[(size_t)(mi*16 + g + 8) * 64 + kb*8 + tg]));
            Qa[mi][kb][2] = __float_as_uint(f2tf32(QSCALE * qp[(size_t)(mi*16 + g    ) * 64 + kb*8 + tg + 4]));
            Qa[mi][kb][3] = __float_as_uint(f2tf32(QSCALE * qp[(size_t)(mi*16 + g + 8) * 64 + kb*8 + tg + 4]));
        }
    }

    float O[2][8][4];
    #pragma unroll
    for (int mi = 0; mi < 2; ++mi)
        #pragma unroll
        for (int nb = 0; nb < 8; ++nb)
            #pragma unroll
            for (int e = 0; e < 4; ++e) O[mi][nb][e] = 0.f;
    float mrow[2][2] = {{-1e30f, -1e30f}, {-1e30f, -1e30f}};
    float lrow[2][2] = {{0.f, 0.f}, {0.f, 0.f}};

    const int njt = 2 * qt + 2;              // >= 2 always

    auto issue = [&](int s, int jt) {
        const int j0 = jt * 64;
        const float* kp = kt0 + (size_t)j0 * HDIM;   // 64 rows (t) x 64 (d)
        float* Kd = KsB + s * K_BUF;
        float* Vd = VsB + s * V_BUF;
        #pragma unroll
        for (int u = 0; u < 8; ++u) {
            const int f = tid + u * 128;
            const int r = f >> 4;
            const int cI = (f & 15) << 2;
            cp16(&Kd[r * K_LD + cI], kp + (size_t)r * HDIM + cI);
            // V^T tile: 64 rows (d) x 64 (t), row stride SEQ
            cp16(&Vd[r * V_LD + cI], vt0 + (size_t)r * SEQ + j0 + cI);
        }
        CP_COMMIT();
    };

    issue(0, 0);
    issue(1, 1);
    CP_WAIT(1);
    __syncthreads();

    for (int jt = 0; jt < njt; ++jt) {
        const int j0 = jt * 64;
        const int st = jt % ASTAGES;
        const float* Kb = KsB + st * K_BUF;
        const float* Vb = VsB + st * V_BUF;

        float s[2][8][4];
        #pragma unroll
        for (int mi = 0; mi < 2; ++mi)
            #pragma unroll
            for (int nb = 0; nb < 8; ++nb)
                #pragma unroll
                for (int e = 0; e < 4; ++e) s[mi][nb][e] = 0.f;

        #pragma unroll
        for (int kb = 0; kb < 8; ++kb) {
            #pragma unroll
            for (int nbp = 0; nbp < 4; ++nbp) {
                const int nb0 = nbp * 2;
                uint32_t b00, b01, b10, b11;
                ldsm4(b00, b01, b10, b11,
                      &Kb[(nb0 * 8 + klm_row) * K_LD + kb * 8 + klm_col]);
                #pragma unroll
                for (int mi = 0; mi < 2; ++mi) {
                    MMA_TF32(s[mi][nb0][0], s[mi][nb0][1], s[mi][nb0][2], s[mi][nb0][3],
                             Qa[mi][kb][0], Qa[mi][kb][1], Qa[mi][kb][2], Qa[mi][kb][3],
                             b00, b01);
                    MMA_TF32(s[mi][nb0+1][0], s[mi][nb0+1][1], s[mi][nb0+1][2], s[mi][nb0+1][3],
                             Qa[mi][kb][0], Qa[mi][kb][1], Qa[mi][kb][2], Qa[mi][kb][3],
                             b10, b11);
                }
            }
        }

        if (jt >= njt - 2) {
            #pragma unroll
            for (int mi = 0; mi < 2; ++mi)
                #pragma unroll
                for (int nb = 0; nb < 8; ++nb)
                    #pragma unroll
                    for (int e = 0; e < 4; ++e) {
                        const int col = j0 + nb * 8 + 2 * tg + (e & 1);
                        const int row = row_base + mi * 16 + g + ((e >> 1) << 3);
                        if (col > row) s[mi][nb][e] = -1e30f;
                    }
        }

        #pragma unroll
        for (int mi = 0; mi < 2; ++mi) {
            float mt0 = mrow[mi][0], mt1 = mrow[mi][1];
            #pragma unroll
            for (int nb = 0; nb < 8; ++nb) {
                mt0 = fmaxf(mt0, fmaxf(s[mi][nb][0], s[mi][nb][1]));
                mt1 = fmaxf(mt1, fmaxf(s[mi][nb][2], s[mi][nb][3]));
            }
            mt0 = fmaxf(mt0, __shfl_xor_sync(0xffffffff, mt0, 1));
            mt0 = fmaxf(mt0, __shfl_xor_sync(0xffffffff, mt0, 2));
            mt1 = fmaxf(mt1, __shfl_xor_sync(0xffffffff, mt1, 1));
            mt1 = fmaxf(mt1, __shfl_xor_sync(0xffffffff, mt1, 2));

            const float al0 = ex2(mrow[mi][0] - mt0);
            const float al1 = ex2(mrow[mi][1] - mt1);
            lrow[mi][0] *= al0; lrow[mi][1] *= al1;
            mrow[mi][0] = mt0;  mrow[mi][1] = mt1;
            #pragma unroll
            for (int nb = 0; nb < 8; ++nb) {
                O[mi][nb][0] *= al0; O[mi][nb][1] *= al0;
                O[mi][nb][2] *= al1; O[mi][nb][3] *= al1;
            }
        }

        const int srcA = (lane & ~3) | (tg >> 1);
        const int srcB = srcA | 2;
        #pragma unroll
        for (int kb = 0; kb < 8; ++kb) {
            uint32_t pa[2][4];
            #pragma unroll
            for (int mi = 0; mi < 2; ++mi) {
                const float p0 = ex2(s[mi][kb][0] - mrow[mi][0]);
                const float p1 = ex2(s[mi][kb][1] - mrow[mi][0]);
                const float p2 = ex2(s[mi][kb][2] - mrow[mi][1]);
                const float p3 = ex2(s[mi][kb][3] - mrow[mi][1]);
                lrow[mi][0] += p0 + p1;
                lrow[mi][1] += p2 + p3;
                const float r0 = f2tf32(p0), r1 = f2tf32(p1);
                const float r2 = f2tf32(p2), r3 = f2tf32(p3);

                const float x0A = __shfl_sync(0xffffffff, r0, srcA);
                const float x1A = __shfl_sync(0xffffffff, r1, srcA);
                const float x0B = __shfl_sync(0xffffffff, r0, srcB);
                const float x1B = __shfl_sync(0xffffffff, r1, srcB);
                const float y0A = __shfl_sync(0xffffffff, r2, srcA);
                const float y1A = __shfl_sync(0xffffffff, r3, srcA);
                const float y0B = __shfl_sync(0xffffffff, r2, srcB);
                const float y1B = __shfl_sync(0xffffffff, r3, srcB);

                pa[mi][0] = __float_as_uint((tg & 1) ? x1A : x0A);
                pa[mi][1] = __float_as_uint((tg & 1) ? y1A : y0A);
                pa[mi][2] = __float_as_uint((tg & 1) ? x1B : x0B);
                pa[mi][3] = __float_as_uint((tg & 1) ? y1B : y0B);
            }

            // V^T B-frags via ldmatrix: Vs[d][t] -> same pattern as K
            #pragma unroll
            for (int nbp = 0; nbp < 4; ++nbp) {
                const int nb0 = nbp * 2;
                uint32_t b00, b01, b10, b11;
                ldsm4(b00, b01, b10, b11,
                      &Vb[(nb0 * 8 + klm_row) * V_LD + kb * 8 + klm_col]);
                #pragma unroll
                for (int mi = 0; mi < 2; ++mi) {
                    MMA_TF32(O[mi][nb0][0], O[mi][nb0][1], O[mi][nb0][2], O[mi][nb0][3],
                             pa[mi][0], pa[mi][1], pa[mi][2], pa[mi][3], b00, b01);
                    MMA_TF32(O[mi][nb0+1][0], O[mi][nb0+1][1], O[mi][nb0+1][2], O[mi][nb0+1][3],
                             pa[mi][0], pa[mi][1], pa[mi][2], pa[mi][3], b10, b11);
                }
            }
        }

        if (jt + 2 < njt) issue((jt + 2) % ASTAGES, jt + 2);
        else              CP_COMMIT();
        CP_WAIT(1);
        __syncthreads();
    }

    #pragma unroll
    for (int mi = 0; mi < 2; ++mi) {
        float l0 = lrow[mi][0], l1 = lrow[mi][1];
        l0 += __shfl_xor_sync(0xffffffff, l0, 1);
        l0 += __shfl_xor_sync(0xffffffff, l0, 2);
        l1 += __shfl_xor_sync(0xffffffff, l1, 1);
        l1 += __shfl_xor_sync(0xffffffff, l1, 2);
        const float inv0 = 1.f / l0;
        const float inv1 = 1.f / l1;

        float* orow0 = out + ((size_t)b * SEQ + row_base + mi*16 + g    ) * CDIM + h * 64;
        float* orow1 = out + ((size_t)b * SEQ + row_base + mi*16 + g + 8) * CDIM + h * 64;
        #pragma unroll
        for (int nb = 0; nb < 8; ++nb) {
            const int cc = nb * 8 + 2 * tg;
            *reinterpret_cast<float2*>(orow0 + cc) =
                make_float2(f2tf32(O[mi][nb][0] * inv0), f2tf32(O[mi][nb][1] * inv0));
            *reinterpret_cast<float2*>(orow1 + cc) =
                make_float2(f2tf32(O[mi][nb][2] * inv1), f2tf32(O[mi][nb][3] * inv1));
        }
    }
}

// ---------------------------------------------------------------------------
// Bridge head. Layout: y[4194304] | bridge_activated[2] | bridge_activations[204]
// ---------------------------------------------------------------------------
__global__ void bridge_kernel(const float* __restrict__ y,
                              const float* __restrict__ Wd,
                              const float* __restrict__ bd,
                              const int* __restrict__ idx32,
                              float* __restrict__ out)
{
    const int b = blockIdx.x;
    const int t = threadIdx.x;           // 128 threads
    __shared__ float red[128];
    __shared__ int is64;

    if (t == 0) {
        int z = 0;
        for (int i = 0; i < BSIZE / 2; ++i) z |= idx32[2 * i + 1];
        is64 = (z == 0) ? 1 : 0;
    }
    __syncthreads();

    float part = 0.f;
    if (t < BSIZE) {
        int c = is64 ? idx32[2 * t] : idx32[t];
        c &= (CDIM - 1);
        const float a = y[((size_t)b * SEQ + (SEQ - 1)) * CDIM + (size_t)c];
        out[(size_t)MROWS * CDIM + BATCH + b * BSIZE + t] = a;
        part = a * Wd[t];
    }
    red[t] = part;
    __syncthreads();
    for (int s = 64; s > 0; s >>= 1) {
        if (t < s) red[t] += red[t + s];
        __syncthreads();
    }
    if (t == 0) {
        const float sig = 1.f / (1.f + __expf(-(red[0] + bd[0])));
        out[(size_t)MROWS * CDIM + b] = (sig > 0.5f) ? 1.0f : 0.0f;
    }
}

// ---------------------------------------------------------------------------
extern "C" void kernel_launch(void* const* d_in, const int* in_sizes, int n_in,
                              void* d_out, int out_size)
{
    const float* x   = (const float*)d_in[0];
    const float* Wq  = (const float*)d_in[1];
    const float* bq  = (const float*)d_in[2];
    const float* Wk  = (const float*)d_in[3];
    const float* bk  = (const float*)d_in[4];
    const float* Wv  = (const float*)d_in[5];
    const float* bv  = (const float*)d_in[6];
    const float* Wp  = (const float*)d_in[7];
    const float* bp  = (const float*)d_in[8];
    const float* Wd  = (const float*)d_in[9];
    const float* bd  = (const float*)d_in[10];
    const int*   bidx = (const int*)d_in[11];
    float* out = (float*)d_out;

    float *gqkv, *gatt, *gxr, *gwr;
    cudaGetSymbolAddress((void**)&gqkv, g_qkv);
    cudaGetSymbolAddress((void**)&gatt, g_att);
    cudaGetSymbolAddress((void**)&gxr, g_xr);
    cudaGetSymbolAddress((void**)&gwr, g_wr);

    static int attr_set = 0;
    if (!attr_set) {
        cudaFuncSetAttribute(gemm_qkv,
                             cudaFuncAttributeMaxDynamicSharedMemorySize, GSMEM);
        cudaFuncSetAttribute(gemm_proj,
                             cudaFuncAttributeMaxDynamicSharedMemorySize, GSMEM);
        cudaFuncSetAttribute(attn_tc,
                             cudaFuncAttributeMaxDynamicSharedMemorySize, ASMEM);
        attr_set = 1;
    }

    // 1) fused tf32 pre-rounding (x + 4 weights)
    prep_round<<<dim3(160, 5), 256>>>(
        (const float4*)x, (const float4*)Wq, (const float4*)Wk,
        (const float4*)Wv, (const float4*)Wp, (float4*)gxr, (float4*)gwr);

    // 2) fused QKV projection (V scattered transposed)
    const int WSZ = CDIM * CDIM;
    gemm_qkv<<<dim3(CDIM / BN, MROWS / BM, 3), 128, GSMEM>>>(
        gxr, gwr, bq, bk, bv, gqkv);

    // 3) attention
    attn_tc<<<dim3(SEQ / 128, BATCH * NHEAD), 128, ASMEM>>>(gatt);

    // 4) output projection
    gemm_proj<<<dim3(CDIM / BN, MROWS / BM), 128, GSMEM>>>(
        gatt, gwr + 3 * WSZ, bp, out);

    // 5) bridge head
    bridge_kernel<<<BATCH, 128>>>(out, Wd, bd, bidx, out);
}

// round 17
// speedup vs baseline: 1.0681x; 1.0681x over previous
#include <cuda_runtime.h>
#include <cuda_bf16.h>
#include <cstdint>

// Problem constants
#define BATCH 2
#define SEQ   2048
#define CDIM  1024
#define NHEAD 16
#define HDIM  64
#define MROWS (BATCH*SEQ)      // 4096
#define BSIZE 102
#define QKV_SZ (BATCH*NHEAD*SEQ*HDIM)

// Scratch (device globals: allocation-free)
__device__ float g_qkv[3*QKV_SZ];             // q|k|v in [B,H,T,D] (tf32-rounded)
__device__ float g_att[MROWS*CDIM];           // [B,T,C]  (tf32-rounded)
__device__ float g_xr[MROWS*CDIM];            // tf32-rounded x
__device__ float g_wr[4*CDIM*CDIM];           // tf32-rounded Wq,Wk,Wv,Wp

// ---------------------------------------------------------------------------
// helpers
// ---------------------------------------------------------------------------
__device__ __forceinline__ float f2tf32(float f) {
    uint32_t r;
    asm("cvt.rna.tf32.f32 %0, %1;" : "=r"(r) : "f"(f));
    return __uint_as_float(r);
}

// single-instruction exp2 (MUFU.EX2)
__device__ __forceinline__ float ex2(float x) {
    float r;
    asm("ex2.approx.f32 %0, %1;" : "=f"(r) : "f"(x));
    return r;
}

#define MMA_TF32(c0,c1,c2,c3,a0,a1,a2,a3,b0,b1)                          \
    asm volatile("mma.sync.aligned.m16n8k8.row.col.f32.tf32.tf32.f32 "  \
                 "{%0,%1,%2,%3},{%4,%5,%6,%7},{%8,%9},{%0,%1,%2,%3};"   \
                 : "+f"(c0), "+f"(c1), "+f"(c2), "+f"(c3)               \
                 : "r"(a0), "r"(a1), "r"(a2), "r"(a3), "r"(b0), "r"(b1))

__device__ __forceinline__ void ldsm4(uint32_t& r0, uint32_t& r1,
                                      uint32_t& r2, uint32_t& r3,
                                      const void* p) {
    uint32_t s = (uint32_t)__cvta_generic_to_shared(p);
    asm volatile("ldmatrix.sync.aligned.m8n8.x4.shared.b16 {%0,%1,%2,%3}, [%4];"
                 : "=r"(r0), "=r"(r1), "=r"(r2), "=r"(r3) : "r"(s));
}

__device__ __forceinline__ void cp16(void* smem_dst, const void* gptr) {
    uint32_t s = (uint32_t)__cvta_generic_to_shared(smem_dst);
    asm volatile("cp.async.cg.shared.global [%0], [%1], 16;" :: "r"(s), "l"(gptr));
}
#define CP_COMMIT() asm volatile("cp.async.commit_group;")
#define CP_WAIT(n)  asm volatile("cp.async.wait_group %0;" :: "n"(n))

// ---------------------------------------------------------------------------
// Fused prep: round x and the four W's to tf32 in one launch.
// ---------------------------------------------------------------------------
__global__ void prep_round(const float4* __restrict__ x,
                           const float4* __restrict__ wq,
                           const float4* __restrict__ wk,
                           const float4* __restrict__ wv,
                           const float4* __restrict__ wp,
                           float4* __restrict__ xr,
                           float4* __restrict__ wr)
{
    const int seg = blockIdx.y;
    const float4* src;
    float4* dst;
    int n4;
    if (seg == 0) { src = x;  dst = xr; n4 = MROWS * CDIM / 4; }
    else {
        src = (seg == 1) ? wq : (seg == 2) ? wk : (seg == 3) ? wv : wp;
        dst = wr + (size_t)(seg - 1) * (CDIM * CDIM / 4);
        n4  = CDIM * CDIM / 4;
    }
    for (int i = blockIdx.x * blockDim.x + threadIdx.x; i < n4;
         i += gridDim.x * blockDim.x) {
        float4 v = src[i];
        v.x = f2tf32(v.x); v.y = f2tf32(v.y);
        v.z = f2tf32(v.z); v.w = f2tf32(v.w);
        dst[i] = v;
    }
}

// ---------------------------------------------------------------------------
// tf32 tensor-core GEMM body, 3-stage cp.async pipeline (one sync per tile),
// ldmatrix A-frags. C[M,N] = A[M,K] @ W[K,N] + bias.  M=4096, N=K=1024.
// CTA 128x128, K-tile 32, 4 warps (64x64 warp tile), 128 threads, 2 CTA/SM.
// mode 0: scatter rounded output into [B,H,T,D]; mode 1: row-major fp32
// ---------------------------------------------------------------------------
#define BM 128
#define BN 128
#define BK 32
#define AS_LD 36
#define BS_LD 136
#define AS_SZ (BM*AS_LD)                    // 4608 floats
#define BS_SZ (BK*BS_LD)                    // 4352 floats
#define GSTAGES 3
#define GSMEM (GSTAGES*(AS_SZ + BS_SZ)*4)   // 107520 bytes

__device__ __forceinline__
void gemm_body(const float* __restrict__ A, const float* __restrict__ W,
               const float* __restrict__ bias, float* __restrict__ C, int mode)
{
    const int K = CDIM, N = CDIM;
    extern __shared__ float sm[];
    float* As = sm;                          // [3][AS_SZ]
    float* Bs = sm + GSTAGES * AS_SZ;        // [3][BS_SZ]

    const int tid  = threadIdx.x;
    const int rowBase = blockIdx.y * BM;
    const int colBase = blockIdx.x * BN;

    const int w    = tid >> 5;
    const int lane = tid & 31;
    const int g    = lane >> 2;
    const int tg   = lane & 3;
    const int wm   = (w >> 1) * 64;
    const int wn   = (w & 1) * 64;

    const int lm_row = ((lane >> 3) & 1) * 8 + (lane & 7);
    const int lm_col = (lane >> 4) * 4;

    float c[4][8][4] = {};
    const int ntiles = K / BK;

    auto issue = [&](int s, int kt) {
        const int k0 = kt * BK;
        #pragma unroll
        for (int i = 0; i < 8; ++i) {
            const int f = tid + i * 128;
            const int ar = f >> 3, ac = f & 7;
            cp16(&As[s * AS_SZ + ar * AS_LD + ac * 4],
                 &A[(size_t)(rowBase + ar) * K + k0 + ac * 4]);
            const int br = f >> 5, bc = f & 31;
            cp16(&Bs[s * BS_SZ + br * BS_LD + bc * 4],
                 &W[(size_t)(k0 + br) * N + colBase + bc * 4]);
        }
        CP_COMMIT();
    };

    // prologue: stages 0,1 in flight; tile 0 resident before loop
    issue(0, 0);
    issue(1, 1);
    CP_WAIT(1);
    __syncthreads();

    for (int kt = 0; kt < ntiles; ++kt) {
        const int s = kt % GSTAGES;
        const float* Ab = As + s * AS_SZ;
        const float* Bb = Bs + s * BS_SZ;

        #pragma unroll
        for (int ks = 0; ks < BK / 8; ++ks) {
            const int kb = ks * 8;
            uint32_t af[4][4];
            #pragma unroll
            for (int mi = 0; mi < 4; ++mi) {
                const int r = wm + mi * 16 + lm_row;
                ldsm4(af[mi][0], af[mi][1], af[mi][2], af[mi][3],
                      &Ab[r * AS_LD + kb + lm_col]);
            }
            uint32_t bf[8][2];
            #pragma unroll
            for (int ni = 0; ni < 8; ++ni) {
                const int n0 = wn + ni * 8 + g;
                bf[ni][0] = __float_as_uint(Bb[(kb + tg    ) * BS_LD + n0]);
                bf[ni][1] = __float_as_uint(Bb[(kb + tg + 4) * BS_LD + n0]);
            }
            #pragma unroll
            for (int mi = 0; mi < 4; ++mi)
                #pragma unroll
                for (int ni = 0; ni < 8; ++ni)
                    MMA_TF32(c[mi][ni][0], c[mi][ni][1], c[mi][ni][2], c[mi][ni][3],
                             af[mi][0], af[mi][1], af[mi][2], af[mi][3],
                             bf[ni][0], bf[ni][1]);
        }

        // issue tile kt+2 into the slot all warps finished reading at kt-1
        if (kt + 2 < ntiles) issue((kt + 2) % GSTAGES, kt + 2);
        else                 CP_COMMIT();          // keep group count aligned
        CP_WAIT(1);                                 // tile kt+1 resident
        __syncthreads();
    }

    #pragma unroll
    for (int mi = 0; mi < 4; ++mi) {
        #pragma unroll
        for (int ni = 0; ni < 8; ++ni) {
            #pragma unroll
            for (int e = 0; e < 4; ++e) {
                const int r  = rowBase + wm + mi * 16 + g + ((e >> 1) << 3);
                const int cc = colBase + wn + ni * 8 + 2 * tg + (e & 1);
                const float val = c[mi][ni][e] + bias[cc];
                if (mode == 0) {
                    const int b = r >> 11;
                    const int t = r & (SEQ - 1);
                    const int h = cc >> 6;
                    const int d = cc & (HDIM - 1);
                    C[(((size_t)b * NHEAD + h) * SEQ + t) * HDIM + d] = f2tf32(val);
                } else {
                    C[(size_t)r * CDIM + cc] = val;
                }
            }
        }
    }
}

// Fused QKV GEMM: grid.z in {0,1,2} selects weight/bias/output slice.
__global__ __launch_bounds__(128)
void gemm_qkv(const float* __restrict__ A, const float* __restrict__ Wbase,
              const float* __restrict__ b0, const float* __restrict__ b1,
              const float* __restrict__ b2, float* __restrict__ outBase)
{
    const int z = blockIdx.z;
    const float* bias = (z == 0) ? b0 : (z == 1) ? b1 : b2;
    gemm_body(A, Wbase + (size_t)z * CDIM * CDIM, bias,
              outBase + (size_t)z * QKV_SZ, 0);
}

__global__ __launch_bounds__(128)
void gemm_proj(const float* __restrict__ A, const float* __restrict__ W,
               const float* __restrict__ bias, float* __restrict__ C)
{
    gemm_body(A, W, bias, C, 1);
}

// ---------------------------------------------------------------------------
// Tensor-core causal flash attention (tf32), 3-stage cp.async pipeline
// (ONE sync per key tile). grid = (SEQ/128, B*H), block = 128.
// Key tile 64. K stride 68 (ldsm conflict-free), V stride 72 (scalar-LDS
// conflict-free). Softmax in exp2 domain via ex2.approx.
// l computed on the tensor pipe: one extra MMA per kb with B = all-ones,
// row sum lands in lacc c0/c2 (all n-columns equal) -> no scalar l adds,
// no end-of-kernel shuffle reduce. P fed raw fp32 (HW tf32 truncation);
// the one-sided bias cancels between P@V and l. Output tf32-rounded.
// ---------------------------------------------------------------------------
#define K_LD 68
#define V_LD 72
#define K_BUF (64*K_LD)                      // 4352 floats
#define V_BUF (64*V_LD)                      // 4608 floats
#define ASTAGES 3
#define ASMEM (ASTAGES*(K_BUF + V_BUF)*4)    // 107520 bytes
#define ONES_TF32 0x3F800000u

__global__ __launch_bounds__(128)
void attn_tc(float* __restrict__ out)
{
    const int qt   = gridDim.x - 1 - blockIdx.x;
    const int bh   = blockIdx.y;
    const int b    = bh >> 4;
    const int h    = bh & 15;
    const int tid  = threadIdx.x;
    const int warp = tid >> 5;
    const int lane = tid & 31;
    const int g    = lane >> 2;
    const int tg   = lane & 3;
    const int row_base = qt * 128 + warp * 32;

    extern __shared__ float smA[];
    float* KsB = smA;                        // [3][K_BUF]
    float* VsB = smA + ASTAGES * K_BUF;      // [3][V_BUF]

    const int klm_row = ((lane >> 4) << 3) + (lane & 7);
    const int klm_col = ((lane >> 3) & 1) * 4;

    const float* kt0 = g_qkv + 1 * QKV_SZ + (size_t)bh * SEQ * HDIM;
    const float* vt0 = g_qkv + 2 * QKV_SZ + (size_t)bh * SEQ * HDIM;

    // Q fragments scaled by (1/8)*log2(e): softmax runs in exp2 domain.
    const float QSCALE = 0.125f * 1.4426950408889634f;
    const float* qp = g_qkv + ((size_t)bh * SEQ + row_base) * HDIM;
    uint32_t Qa[2][8][4];
    #pragma unroll
    for (int mi = 0; mi < 2; ++mi) {
        #pragma unroll
        for (int kb = 0; kb < 8; ++kb) {
            Qa[mi][kb][0] = __float_as_uint(f2tf32(QSCALE * qp[(size_t)(mi*16 + g    ) * 64 + kb*8 + tg]));
            Qa[mi][kb][1] = __float_as_uint(f2tf32(QSCALE * qp[(size_t)(mi*16 + g + 8) * 64 + kb*8 + tg]));
            Qa[mi][kb][2] = __float_as_uint(f2tf32(QSCALE * qp[(size_t)(mi*16 + g    ) * 64 + kb*8 + tg + 4]));
            Qa[mi][kb][3] = __float_as_uint(f2tf32(QSCALE * qp[(size_t)(mi*16 + g + 8) * 64 + kb*8 + tg + 4]));
        }
    }

    float O[2][8][4];
    #pragma unroll
    for (int mi = 0; mi < 2; ++mi)
        #pragma unroll
        for (int nb = 0; nb < 8; ++nb)
            #pragma unroll
            for (int e = 0; e < 4; ++e) O[mi][nb][e] = 0.f;
    float lacc[2][4] = {{0.f,0.f,0.f,0.f},{0.f,0.f,0.f,0.f}};
    float mrow[2][2] = {{-1e30f, -1e30f}, {-1e30f, -1e30f}};

    const int njt = 2 * qt + 2;              // >= 2 always

    auto issue = [&](int s, int jt) {
        const int j0 = jt * 64;
        const float* kp = kt0 + (size_t)j0 * HDIM;
        const float* vp = vt0 + (size_t)j0 * HDIM;
        float* Kd = KsB + s * K_BUF;
        float* Vd = VsB + s * V_BUF;
        #pragma unroll
        for (int u = 0; u < 8; ++u) {
            const int f = tid + u * 128;
            const int r = f >> 4;
            const int cI = (f & 15) << 2;
            cp16(&Kd[r * K_LD + cI], kp + (size_t)r * HDIM + cI);
            cp16(&Vd[r * V_LD + cI], vp + (size_t)r * HDIM + cI);
        }
        CP_COMMIT();
    };

    // prologue: tiles 0,1 in flight; tile 0 resident
    issue(0, 0);
    issue(1, 1);
    CP_WAIT(1);
    __syncthreads();

    for (int jt = 0; jt < njt; ++jt) {
        const int j0 = jt * 64;
        const int st = jt % ASTAGES;
        const float* Kb = KsB + st * K_BUF;
        const float* Vb = VsB + st * V_BUF;

        float s[2][8][4];
        #pragma unroll
        for (int mi = 0; mi < 2; ++mi)
            #pragma unroll
            for (int nb = 0; nb < 8; ++nb)
                #pragma unroll
                for (int e = 0; e < 4; ++e) s[mi][nb][e] = 0.f;

        #pragma unroll
        for (int kb = 0; kb < 8; ++kb) {
            #pragma unroll
            for (int nbp = 0; nbp < 4; ++nbp) {
                const int nb0 = nbp * 2;
                uint32_t b00, b01, b10, b11;
                ldsm4(b00, b01, b10, b11,
                      &Kb[(nb0 * 8 + klm_row) * K_LD + kb * 8 + klm_col]);
                #pragma unroll
                for (int mi = 0; mi < 2; ++mi) {
                    MMA_TF32(s[mi][nb0][0], s[mi][nb0][1], s[mi][nb0][2], s[mi][nb0][3],
                             Qa[mi][kb][0], Qa[mi][kb][1], Qa[mi][kb][2], Qa[mi][kb][3],
                             b00, b01);
                    MMA_TF32(s[mi][nb0+1][0], s[mi][nb0+1][1], s[mi][nb0+1][2], s[mi][nb0+1][3],
                             Qa[mi][kb][0], Qa[mi][kb][1], Qa[mi][kb][2], Qa[mi][kb][3],
                             b10, b11);
                }
            }
        }

        // causal mask (only last two tiles can cross the diagonal)
        if (jt >= njt - 2) {
            #pragma unroll
            for (int mi = 0; mi < 2; ++mi)
                #pragma unroll
                for (int nb = 0; nb < 8; ++nb)
                    #pragma unroll
                    for (int e = 0; e < 4; ++e) {
                        const int col = j0 + nb * 8 + 2 * tg + (e & 1);
                        const int row = row_base + mi * 16 + g + ((e >> 1) << 3);
                        if (col > row) s[mi][nb][e] = -1e30f;
                    }
        }

        // online softmax per m-block (exp2 domain, single-instr ex2)
        #pragma unroll
        for (int mi = 0; mi < 2; ++mi) {
            float mt0 = mrow[mi][0], mt1 = mrow[mi][1];
            #pragma unroll
            for (int nb = 0; nb < 8; ++nb) {
                mt0 = fmaxf(mt0, fmaxf(s[mi][nb][0], s[mi][nb][1]));
                mt1 = fmaxf(mt1, fmaxf(s[mi][nb][2], s[mi][nb][3]));
            }
            mt0 = fmaxf(mt0, __shfl_xor_sync(0xffffffff, mt0, 1));
            mt0 = fmaxf(mt0, __shfl_xor_sync(0xffffffff, mt0, 2));
            mt1 = fmaxf(mt1, __shfl_xor_sync(0xffffffff, mt1, 1));
            mt1 = fmaxf(mt1, __shfl_xor_sync(0xffffffff, mt1, 2));

            const float al0 = ex2(mrow[mi][0] - mt0);
            const float al1 = ex2(mrow[mi][1] - mt1);
            mrow[mi][0] = mt0;  mrow[mi][1] = mt1;
            lacc[mi][0] *= al0; lacc[mi][2] *= al1;   // only read elements
            #pragma unroll
            for (int nb = 0; nb < 8; ++nb) {
                O[mi][nb][0] *= al0; O[mi][nb][1] *= al0;
                O[mi][nb][2] *= al1; O[mi][nb][3] *= al1;
            }
        }

        // P = ex2(S-m) raw fp32; C-frag -> A-frag via shuffles;
        // l += P@ones (tensor); O += P @ V
        const int srcA = (lane & ~3) | (tg >> 1);
        const int srcB = srcA | 2;
        #pragma unroll
        for (int kb = 0; kb < 8; ++kb) {
            uint32_t pa[2][4];
            #pragma unroll
            for (int mi = 0; mi < 2; ++mi) {
                const float r0 = ex2(s[mi][kb][0] - mrow[mi][0]);
                const float r1 = ex2(s[mi][kb][1] - mrow[mi][0]);
                const float r2 = ex2(s[mi][kb][2] - mrow[mi][1]);
                const float r3 = ex2(s[mi][kb][3] - mrow[mi][1]);

                const float x0A = __shfl_sync(0xffffffff, r0, srcA);
                const float x1A = __shfl_sync(0xffffffff, r1, srcA);
                const float x0B = __shfl_sync(0xffffffff, r0, srcB);
                const float x1B = __shfl_sync(0xffffffff, r1, srcB);
                const float y0A = __shfl_sync(0xffffffff, r2, srcA);
                const float y1A = __shfl_sync(0xffffffff, r3, srcA);
                const float y0B = __shfl_sync(0xffffffff, r2, srcB);
                const float y1B = __shfl_sync(0xffffffff, r3, srcB);

                pa[mi][0] = __float_as_uint((tg & 1) ? x1A : x0A);
                pa[mi][1] = __float_as_uint((tg & 1) ? y1A : y0A);
                pa[mi][2] = __float_as_uint((tg & 1) ? x1B : x0B);
                pa[mi][3] = __float_as_uint((tg & 1) ? y1B : y0B);

                // l row-sum on the tensor pipe (B = ones)
                MMA_TF32(lacc[mi][0], lacc[mi][1], lacc[mi][2], lacc[mi][3],
                         pa[mi][0], pa[mi][1], pa[mi][2], pa[mi][3],
                         ONES_TF32, ONES_TF32);
            }

            #pragma unroll
            for (int nb = 0; nb < 8; ++nb) {
                const uint32_t b0 = __float_as_uint(Vb[(kb * 8 + tg    ) * V_LD + nb * 8 + g]);
                const uint32_t b1 = __float_as_uint(Vb[(kb * 8 + tg + 4) * V_LD + nb * 8 + g]);
                #pragma unroll
                for (int mi = 0; mi < 2; ++mi)
                    MMA_TF32(O[mi][nb][0], O[mi][nb][1], O[mi][nb][2], O[mi][nb][3],
                             pa[mi][0], pa[mi][1], pa[mi][2], pa[mi][3], b0, b1);
            }
        }

        // issue tile jt+2 into the slot all warps finished reading at jt-1
        if (jt + 2 < njt) issue((jt + 2) % ASTAGES, jt + 2);
        else              CP_COMMIT();
        CP_WAIT(1);
        __syncthreads();
    }

    // epilogue: l already full row-sums in lacc c0/c2 (no reduce needed)
    #pragma unroll
    for (int mi = 0; mi < 2; ++mi) {
        const float inv0 = 1.f / lacc[mi][0];
        const float inv1 = 1.f / lacc[mi][2];

        float* orow0 = out + ((size_t)b * SEQ + row_base + mi*16 + g    ) * CDIM + h * 64;
        float* orow1 = out + ((size_t)b * SEQ + row_base + mi*16 + g + 8) * CDIM + h * 64;
        #pragma unroll
        for (int nb = 0; nb < 8; ++nb) {
            const int cc = nb * 8 + 2 * tg;
            *reinterpret_cast<float2*>(orow0 + cc) =
                make_float2(f2tf32(O[mi][nb][0] * inv0), f2tf32(O[mi][nb][1] * inv0));
            *reinterpret_cast<float2*>(orow1 + cc) =
                make_float2(f2tf32(O[mi][nb][2] * inv1), f2tf32(O[mi][nb][3] * inv1));
        }
    }
}

// ---------------------------------------------------------------------------
// Bridge head. Layout: y[4194304] | bridge_activated[2] | bridge_activations[204]
// ---------------------------------------------------------------------------
__global__ void bridge_kernel(const float* __restrict__ y,
                              const float* __restrict__ Wd,
                              const float* __restrict__ bd,
                              const int* __restrict__ idx32,
                              float* __restrict__ out)
{
    const int b = blockIdx.x;
    const int t = threadIdx.x;           // 128 threads
    __shared__ float red[128];
    __shared__ int is64;

    if (t == 0) {
        int z = 0;
        for (int i = 0; i < BSIZE / 2; ++i) z |= idx32[2 * i + 1];
        is64 = (z == 0) ? 1 : 0;
    }
    __syncthreads();

    float part = 0.f;
    if (t < BSIZE) {
        int c = is64 ? idx32[2 * t] : idx32[t];
        c &= (CDIM - 1);
        const float a = y[((size_t)b * SEQ + (SEQ - 1)) * CDIM + (size_t)c];
        out[(size_t)MROWS * CDIM + BATCH + b * BSIZE + t] = a;
        part = a * Wd[t];
    }
    red[t] = part;
    __syncthreads();
    for (int s = 64; s > 0; s >>= 1) {
        if (t < s) red[t] += red[t + s];
        __syncthreads();
    }
    if (t == 0) {
        const float sig = 1.f / (1.f + __expf(-(red[0] + bd[0])));
        out[(size_t)MROWS * CDIM + b] = (sig > 0.5f) ? 1.0f : 0.0f;
    }
}

// ---------------------------------------------------------------------------
extern "C" void kernel_launch(void* const* d_in, const int* in_sizes, int n_in,
                              void* d_out, int out_size)
{
    const float* x   = (const float*)d_in[0];
    const float* Wq  = (const float*)d_in[1];
    const float* bq  = (const float*)d_in[2];
    const float* Wk  = (const float*)d_in[3];
    const float* bk  = (const float*)d_in[4];
    const float* Wv  = (const float*)d_in[5];
    const float* bv  = (const float*)d_in[6];
    const float* Wp  = (const float*)d_in[7];
    const float* bp  = (const float*)d_in[8];
    const float* Wd  = (const float*)d_in[9];
    const float* bd  = (const float*)d_in[10];
    const int*   bidx = (const int*)d_in[11];
    float* out = (float*)d_out;

    float *gqkv, *gatt, *gxr, *gwr;
    cudaGetSymbolAddress((void**)&gqkv, g_qkv);
    cudaGetSymbolAddress((void**)&gatt, g_att);
    cudaGetSymbolAddress((void**)&gxr, g_xr);
    cudaGetSymbolAddress((void**)&gwr, g_wr);

    static int attr_set = 0;
    if (!attr_set) {
        cudaFuncSetAttribute(gemm_qkv,
                             cudaFuncAttributeMaxDynamicSharedMemorySize, GSMEM);
        cudaFuncSetAttribute(gemm_proj,
                             cudaFuncAttributeMaxDynamicSharedMemorySize, GSMEM);
        cudaFuncSetAttribute(attn_tc,
                             cudaFuncAttributeMaxDynamicSharedMemorySize, ASMEM);
        attr_set = 1;
    }

    // 1) fused tf32 pre-rounding (x + 4 weights)
    prep_round<<<dim3(256, 5), 256>>>(
        (const float4*)x, (const float4*)Wq, (const float4*)Wk,
        (const float4*)Wv, (const float4*)Wp, (float4*)gxr, (float4*)gwr);

    // 2) fused QKV projection  (grid = 8 x 32 x 3 = 768 CTAs)
    const int WSZ = CDIM * CDIM;
    gemm_qkv<<<dim3(CDIM / BN, MROWS / BM, 3), 128, GSMEM>>>(
        gxr, gwr, bq, bk, bv, gqkv);

    // 3) attention
    attn_tc<<<dim3(SEQ / 128, BATCH * NHEAD), 128, ASMEM>>>(gatt);

    // 4) output projection  (grid = 8 x 32 = 256 CTAs)
    gemm_proj<<<dim3(CDIM / BN, MROWS / BM), 128, GSMEM>>>(
        gatt, gwr + 3 * WSZ, bp, out);

    // 5) bridge head
    bridge_kernel<<<BATCH, 128>>>(out, Wd, bd, bidx, out);
}